// round 7
// baseline (speedup 1.0000x reference)
#include <cuda_runtime.h>
#include <cstddef>
#include <math.h>

#define DMODEL 1024
#define NTOK   4096
#define FFDIM  4096
#define SEQ    1024
#define REC_CTAS 128

__device__ float g_xn [NTOK*DMODEL];
__device__ float g_q  [NTOK*DMODEL];
__device__ float g_k  [NTOK*DMODEL];
__device__ float g_v  [NTOK*DMODEL];
__device__ float g_z  [NTOK*DMODEL];
__device__ float g_gm [NTOK*DMODEL];
__device__ float g_t1 [NTOK*128];
__device__ float g_h  [NTOK*DMODEL];
__device__ float g_att[NTOK*DMODEL];
__device__ float g_ao [NTOK*DMODEL];
__device__ float g_y  [NTOK*DMODEL];
__device__ float g_yn [NTOK*DMODEL];
__device__ float g_f1 [NTOK*FFDIM];
__device__ unsigned g_bar_count;
__device__ unsigned g_bar_sense;

// 32 per-lane accumulators -> lane l ends with full-warp sum of acc[l]. 31 shfls.
__device__ __forceinline__ float multi_reduce32(float (&acc)[32], int lane) {
#pragma unroll
    for (int d = 16; d >= 1; d >>= 1) {
        const bool up = (lane & d) != 0;
#pragma unroll
        for (int i = 0; i < d; i++) {
            float send = up ? acc[i] : acc[i + d];
            float recv = __shfl_xor_sync(0xffffffffu, send, d);
            float keep = up ? acc[i + d] : acc[i];
            acc[i] = keep + recv;
        }
    }
    return acc[0];
}

__device__ __forceinline__ float block_sum256(float v) {
    __shared__ float sred[9];
#pragma unroll
    for (int o = 16; o; o >>= 1) v += __shfl_xor_sync(0xffffffffu, v, o);
    int w = threadIdx.x >> 5, l = threadIdx.x & 31;
    if (l == 0) sred[w] = v;
    __syncthreads();
    if (threadIdx.x < 32) {
        float t = (l < 8) ? sred[l] : 0.f;
#pragma unroll
        for (int o = 4; o; o >>= 1) t += __shfl_xor_sync(0xffffffffu, t, o);
        if (l == 0) sred[8] = t;
    }
    __syncthreads();
    return sred[8];
}

__global__ __launch_bounds__(256)
void rmsnorm_kernel(const float* __restrict__ x, const float* __restrict__ w,
                    float* __restrict__ out) {
    const size_t base = (size_t)blockIdx.x * DMODEL;
    float vb[4]; float ss = 0.f;
#pragma unroll
    for (int i = 0; i < 4; i++) { float t = x[base + threadIdx.x + 256*i]; vb[i] = t; ss += t*t; }
    float inv = 1.f / (sqrtf(block_sum256(ss)) * 0.03125f + 1e-6f);
#pragma unroll
    for (int i = 0; i < 4; i++) { int c = threadIdx.x + 256*i; out[base + c] = w[c] * vb[i] * inv; }
}

// y = x + ao + h ; yn = rmsnorm(y)
__global__ __launch_bounds__(256)
void residual_norm_kernel(const float* __restrict__ x, const float* __restrict__ ao,
                          const float* __restrict__ hs, const float* __restrict__ w,
                          float* __restrict__ y, float* __restrict__ yn) {
    const size_t base = (size_t)blockIdx.x * DMODEL;
    float vb[4]; float ss = 0.f;
#pragma unroll
    for (int i = 0; i < 4; i++) {
        int c = threadIdx.x + 256*i;
        float t = x[base+c] + ao[base+c] + hs[base+c];
        vb[i] = t; y[base+c] = t; ss += t*t;
    }
    float inv = 1.f / (sqrtf(block_sum256(ss)) * 0.03125f + 1e-6f);
#pragma unroll
    for (int i = 0; i < 4; i++) { int c = threadIdx.x + 256*i; yn[base+c] = w[c] * vb[i] * inv; }
}

// C[M,N] = A[M,K] @ B[N,K]^T + bias ; EPI 0=none 1=relu 2=sigmoid+clip 3=gelu ; +res
template<int EPI>
__global__ __launch_bounds__(256, 2)
void sgemm_kernel(const float* __restrict__ A, const float* __restrict__ B,
                  const float* __restrict__ bias, const float* __restrict__ res,
                  float* __restrict__ C, int M, int N, int K)
{
    __shared__ __align__(16) float As[8][128];
    __shared__ __align__(16) float Bs[8][128];
    const int tid = threadIdx.x;
    const int bm = blockIdx.y * 128, bn = blockIdx.x * 128;
    const int row0 = (tid >> 4) * 8, col0 = (tid & 15) * 8;
    const int arow = tid >> 1, ak = (tid & 1) * 4;
    const float* Ap = A + (size_t)(bm + arow) * K + ak;
    const float* Bp = B + (size_t)(bn + arow) * K + ak;

    float acc[8][8];
#pragma unroll
    for (int i = 0; i < 8; i++)
#pragma unroll
        for (int j = 0; j < 8; j++) acc[i][j] = 0.f;

    for (int kt = 0; kt < K; kt += 8) {
        float4 av = *(const float4*)(Ap + kt);
        float4 bv = *(const float4*)(Bp + kt);
        As[ak+0][arow]=av.x; As[ak+1][arow]=av.y; As[ak+2][arow]=av.z; As[ak+3][arow]=av.w;
        Bs[ak+0][arow]=bv.x; Bs[ak+1][arow]=bv.y; Bs[ak+2][arow]=bv.z; Bs[ak+3][arow]=bv.w;
        __syncthreads();
#pragma unroll
        for (int kk = 0; kk < 8; kk++) {
            float4 a0 = *(const float4*)&As[kk][row0];
            float4 a1 = *(const float4*)&As[kk][row0+4];
            float4 b0 = *(const float4*)&Bs[kk][col0];
            float4 b1 = *(const float4*)&Bs[kk][col0+4];
            float ar[8] = {a0.x,a0.y,a0.z,a0.w,a1.x,a1.y,a1.z,a1.w};
            float br[8] = {b0.x,b0.y,b0.z,b0.w,b1.x,b1.y,b1.z,b1.w};
#pragma unroll
            for (int i = 0; i < 8; i++)
#pragma unroll
                for (int j = 0; j < 8; j++)
                    acc[i][j] = fmaf(ar[i], br[j], acc[i][j]);
        }
        __syncthreads();
    }
#pragma unroll
    for (int i = 0; i < 8; i++) {
        const int gr = bm + row0 + i;
        float* crow = C + (size_t)gr * N;
        const float* rrow = res ? res + (size_t)gr * N : nullptr;
#pragma unroll
        for (int j = 0; j < 8; j++) {
            const int gc = bn + col0 + j;
            float vv = acc[i][j] + bias[gc];
            if (EPI == 1) vv = fmaxf(vv, 0.f);
            else if (EPI == 2) {
                vv = 1.f / (1.f + __expf(-vv));
                vv = fminf(fmaxf(vv, 1e-6f), 1.f - 1e-6f);
            } else if (EPI == 3) {
                float u = 0.7978845608028654f * (vv + 0.044715f * vv * vv * vv);
                vv = 0.5f * vv * (1.f + tanhf(u));
            }
            if (rrow) vv += rrow[gc];
            crow[gc] = vv;
        }
    }
}

// h_t = z_t * sigmoid(h_{t-1} @ Wg^T + bg) + gamma_t * h_{t-1}. Persistent, 128 CTAs.
__global__ __launch_bounds__(256, 1)
void recurrence_kernel(const float* __restrict__ z, const float* __restrict__ gm,
                       const float* __restrict__ Wg, const float* __restrict__ bg,
                       float* __restrict__ hs)
{
    const int tid = threadIdx.x, w = tid >> 5, l = tid & 31;
    const int blk = blockIdx.x;
    const int k0 = w * 128 + l * 4;
    float4 wv[8];
#pragma unroll
    for (int r = 0; r < 8; r++)
        wv[r] = *(const float4*)(Wg + (size_t)(blk*8 + r) * DMODEL + k0);

    __shared__ float red[256];
    float bgv = 0.f, hprev = 0.f; int jout = 0, bout = 0;
    if (tid < 32) { jout = blk*8 + (tid >> 2); bout = tid & 3; bgv = bg[jout]; }

    for (int t = 0; t < SEQ; t++) {
        float acc[32];
#pragma unroll
        for (int a = 0; a < 32; a++) acc[a] = 0.f;
        if (t > 0) {
#pragma unroll
            for (int b = 0; b < 4; b++) {
                float4 hv = __ldcg((const float4*)(hs + ((size_t)b*SEQ + (t-1))*DMODEL + k0));
#pragma unroll
                for (int r = 0; r < 8; r++) {
                    acc[r*4+b] = fmaf(wv[r].x, hv.x, acc[r*4+b]);
                    acc[r*4+b] = fmaf(wv[r].y, hv.y, acc[r*4+b]);
                    acc[r*4+b] = fmaf(wv[r].z, hv.z, acc[r*4+b]);
                    acc[r*4+b] = fmaf(wv[r].w, hv.w, acc[r*4+b]);
                }
            }
        }
        float part = multi_reduce32(acc, l);      // lane l: warp-partial for (r=l>>2, b=l&3)
        red[w*32 + l] = part;
        __syncthreads();
        if (tid < 32) {
            float sum = bgv;
#pragma unroll
            for (int ww = 0; ww < 8; ww++) sum += red[ww*32 + tid];
            float sig = 1.f / (1.f + __expf(-sum));
            size_t base = ((size_t)bout * SEQ + t) * DMODEL + jout;
            hprev = z[base] * sig + gm[base] * hprev;
            hs[base] = hprev;
            __threadfence();
        }
        __syncthreads();
        if (tid == 0) {      // sense-reversing grid barrier (all CTAs co-resident)
            unsigned sv = *(volatile unsigned*)&g_bar_sense;
            unsigned prev = atomicAdd(&g_bar_count, 1u);
            if (prev == REC_CTAS - 1) {
                g_bar_count = 0;
                __threadfence();
                atomicExch(&g_bar_sense, sv ^ 1u);
            } else {
                while (*(volatile unsigned*)&g_bar_sense == sv) { }
            }
            __threadfence();
        }
        __syncthreads();
    }
}

// block = (b, h, 8 q-rows); warp w <-> q row; lane l <-> k rows l+32i. Scores in regs.
__global__ __launch_bounds__(256)
void attn_kernel(const float* __restrict__ q, const float* __restrict__ k,
                 const float* __restrict__ v, float* __restrict__ ao)
{
    const int qb = blockIdx.x & 127;
    const int bh = blockIdx.x >> 7;
    const int b = bh >> 4, h = bh & 15;
    __shared__ float Qs[8][64];
    __shared__ float Ts[64*65];
    const int tid = threadIdx.x, w = tid >> 5, l = tid & 31;
    const size_t bbase = (size_t)b * SEQ * DMODEL + (size_t)h * 64;
    const int qrow0 = qb * 8;

    for (int idx = tid; idx < 8*64; idx += 256)
        Qs[idx>>6][idx&63] = q[bbase + (size_t)(qrow0 + (idx>>6)) * DMODEL + (idx&63)];

    float p[32];
#pragma unroll 1
    for (int j = 0; j < 16; j++) {
        __syncthreads();
        for (int idx = tid; idx < 64*64; idx += 256)
            Ts[(idx>>6)*65 + (idx&63)] = k[bbase + (size_t)(j*64 + (idx>>6)) * DMODEL + (idx&63)];
        __syncthreads();
#pragma unroll
        for (int ii = 0; ii < 2; ii++) {
            const int kr = l + 32*ii;
            float s = 0.f;
#pragma unroll
            for (int d = 0; d < 64; d++) s = fmaf(Qs[w][d], Ts[kr*65 + d], s);
            p[2*j + ii] = s * 0.125f;
        }
    }
    float m = -3.0e38f;
#pragma unroll
    for (int i = 0; i < 32; i++) m = fmaxf(m, p[i]);
#pragma unroll
    for (int o = 16; o; o >>= 1) m = fmaxf(m, __shfl_xor_sync(0xffffffffu, m, o));
    float s = 0.f;
#pragma unroll
    for (int i = 0; i < 32; i++) { p[i] = __expf(p[i] - m); s += p[i]; }
#pragma unroll
    for (int o = 16; o; o >>= 1) s += __shfl_xor_sync(0xffffffffu, s, o);
    float inv = 1.f / s;
#pragma unroll
    for (int i = 0; i < 32; i++) p[i] *= inv;

    float o0[32], o1[32];
#pragma unroll
    for (int i = 0; i < 32; i++) { o0[i] = 0.f; o1[i] = 0.f; }
#pragma unroll 1
    for (int j = 0; j < 16; j++) {
        __syncthreads();
        for (int idx = tid; idx < 64*64; idx += 256)
            Ts[(idx>>6)*65 + (idx&63)] = v[bbase + (size_t)(j*64 + (idx>>6)) * DMODEL + (idx&63)];
        __syncthreads();
#pragma unroll
        for (int ii = 0; ii < 2; ii++) {
            const int kr = l + 32*ii;
            const float pi = p[2*j + ii];
#pragma unroll
            for (int d = 0; d < 32; d++) o0[d] = fmaf(pi, Ts[kr*65 + d],      o0[d]);
#pragma unroll
            for (int d = 0; d < 32; d++) o1[d] = fmaf(pi, Ts[kr*65 + 32 + d], o1[d]);
        }
    }
    float r0 = multi_reduce32(o0, l);
    float r1 = multi_reduce32(o1, l);
    size_t ob = bbase + (size_t)(qrow0 + w) * DMODEL;
    ao[ob + l] = r0;
    ao[ob + 32 + l] = r1;
}

extern "C" void kernel_launch(void* const* d_in, const int* in_sizes, int n_in,
                              void* d_out, int out_size)
{
    (void)in_sizes; (void)n_in; (void)out_size;
    const float* x   = (const float*)d_in[0];
    const float* n1w = (const float*)d_in[1];
    const float* Wq  = (const float*)d_in[2];  const float* bq = (const float*)d_in[3];
    const float* Wk  = (const float*)d_in[4];  const float* bk = (const float*)d_in[5];
    const float* Wv  = (const float*)d_in[6];  const float* bv = (const float*)d_in[7];
    const float* Wz  = (const float*)d_in[8];  const float* bz = (const float*)d_in[9];
    const float* Wg  = (const float*)d_in[10]; const float* bg = (const float*)d_in[11];
    const float* gdw = (const float*)d_in[12]; const float* gdb= (const float*)d_in[13];
    const float* guw = (const float*)d_in[14]; const float* gub= (const float*)d_in[15];
    const float* Wo  = (const float*)d_in[16]; const float* bo = (const float*)d_in[17];
    const float* n2w = (const float*)d_in[18];
    const float* f1w = (const float*)d_in[19]; const float* f1b= (const float*)d_in[20];
    const float* f2w = (const float*)d_in[21]; const float* f2b= (const float*)d_in[22];
    float* out = (float*)d_out;

    float *xn, *qp, *kp, *vp, *zp, *gmp, *t1, *hp, *attp, *aop, *yp, *ynp, *f1p;
    cudaGetSymbolAddress((void**)&xn,  g_xn);
    cudaGetSymbolAddress((void**)&qp,  g_q);
    cudaGetSymbolAddress((void**)&kp,  g_k);
    cudaGetSymbolAddress((void**)&vp,  g_v);
    cudaGetSymbolAddress((void**)&zp,  g_z);
    cudaGetSymbolAddress((void**)&gmp, g_gm);
    cudaGetSymbolAddress((void**)&t1,  g_t1);
    cudaGetSymbolAddress((void**)&hp,  g_h);
    cudaGetSymbolAddress((void**)&attp,g_att);
    cudaGetSymbolAddress((void**)&aop, g_ao);
    cudaGetSymbolAddress((void**)&yp,  g_y);
    cudaGetSymbolAddress((void**)&ynp, g_yn);
    cudaGetSymbolAddress((void**)&f1p, g_f1);

    // 1. rmsnorm
    rmsnorm_kernel<<<NTOK, 256>>>(x, n1w, xn);
    // 2. Q/K/V/Z projections
    dim3 gDD(DMODEL/128, NTOK/128);
    sgemm_kernel<0><<<gDD, 256>>>(xn, Wq, bq, nullptr, qp, NTOK, DMODEL, DMODEL);
    sgemm_kernel<0><<<gDD, 256>>>(xn, Wk, bk, nullptr, kp, NTOK, DMODEL, DMODEL);
    sgemm_kernel<0><<<gDD, 256>>>(xn, Wv, bv, nullptr, vp, NTOK, DMODEL, DMODEL);
    sgemm_kernel<0><<<gDD, 256>>>(xn, Wz, bz, nullptr, zp, NTOK, DMODEL, DMODEL);
    // 3. gamma = clip(sigmoid(relu(z@gdw^T+gdb)@guw^T+gub))
    sgemm_kernel<1><<<dim3(1, NTOK/128), 256>>>(zp, gdw, gdb, nullptr, t1, NTOK, 128, DMODEL);
    sgemm_kernel<2><<<gDD, 256>>>(t1, guw, gub, nullptr, gmp, NTOK, DMODEL, 128);
    // 4. recurrence (persistent grid)
    recurrence_kernel<<<REC_CTAS, 256>>>(zp, gmp, Wg, bg, hp);
    // 5. attention + Wo
    attn_kernel<<<4*16*128, 256>>>(qp, kp, vp, attp);
    sgemm_kernel<0><<<gDD, 256>>>(attp, Wo, bo, nullptr, aop, NTOK, DMODEL, DMODEL);
    // 6-7. residual + norm2, FFN, final residual (-> d_out)
    residual_norm_kernel<<<NTOK, 256>>>(x, aop, hp, n2w, yp, ynp);
    sgemm_kernel<3><<<dim3(FFDIM/128, NTOK/128), 256>>>(ynp, f1w, f1b, nullptr, f1p, NTOK, FFDIM, DMODEL);
    sgemm_kernel<0><<<gDD, 256>>>(f1p, f2w, f2b, yp, out, NTOK, DMODEL, FFDIM);
}